// round 7
// baseline (speedup 1.0000x reference)
#include <cuda_runtime.h>
#include <cstdint>

// ---------------------------------------------------------------------------
// BiLSTM-CRF: gather -> input GEMM -> cluster-resident LSTM (fwd+bwd as two
// 8-CTA clusters, register W_hh packed f32x2, DSMEM bulk-copy h-exchange,
// single-waiter mbarrier) -> linear -> CRF forward + Viterbi.
// ---------------------------------------------------------------------------

#define SEQ   4096
#define EMB   500
#define HID   200
#define G4    800      // 4*HID
#define NT    50
#define TSTART 48
#define TEND   49
#define NEGV  (-10000.0f)
#define NBLK  8        // CTAs per direction (= cluster size)
#define JS    25       // HID / NBLK
#define ROWS  100      // 4*JS gate rows per CTA
#define HP    28       // padded slice floats (112 B, 16B multiple)
#define HPAD  (NBLK * HP)        // 224
#define SLICE_BYTES (HP * 4)     // 112
#define TXB   (NBLK * SLICE_BYTES) // 896

// ------------------------------ scratch -----------------------------------
__device__ float g_x[SEQ * EMB];
__device__ float g_xproj[2][SEQ * G4];
__device__ float g_hseq[2][SEQ * HID];
__device__ float g_feats[SEQ * NT];

// --------------------------- PTX helpers -----------------------------------
__device__ __forceinline__ uint32_t smem_u32(const void* p) {
    uint32_t a;
    asm("{ .reg .u64 t; cvta.to.shared.u64 t, %1; cvt.u32.u64 %0, t; }"
        : "=r"(a) : "l"(p));
    return a;
}
__device__ __forceinline__ uint32_t mapa32(uint32_t a, uint32_t rank) {
    uint32_t d;
    asm("mapa.shared::cluster.u32 %0, %1, %2;" : "=r"(d) : "r"(a), "r"(rank));
    return d;
}
__device__ __forceinline__ void mbar_init(uint32_t a, uint32_t n) {
    asm volatile("mbarrier.init.shared.b64 [%0], %1;" :: "r"(a), "r"(n) : "memory");
}
__device__ __forceinline__ void mbar_arrive_expect_tx(uint32_t a, uint32_t tx) {
    asm volatile("mbarrier.arrive.expect_tx.shared.b64 _, [%0], %1;"
                 :: "r"(a), "r"(tx) : "memory");
}
__device__ __forceinline__ void mbar_wait_cluster_acq(uint32_t a, uint32_t ph) {
    asm volatile(
        "{\n\t.reg .pred P;\n"
        "LW_%=:\n\t"
        "mbarrier.try_wait.parity.acquire.cluster.shared::cta.b64 P, [%0], %1, 0x989680;\n\t"
        "@P bra LD_%=;\n\t"
        "bra LW_%=;\n"
        "LD_%=:\n\t}"
        :: "r"(a), "r"(ph) : "memory");
}
__device__ __forceinline__ void dsmem_bulk_copy(uint32_t dst_cluster, uint32_t src_cta,
                                                uint32_t bytes, uint32_t rmbar) {
    asm volatile(
        "cp.async.bulk.shared::cluster.shared::cta.mbarrier::complete_tx::bytes "
        "[%0], [%1], %2, [%3];"
        :: "r"(dst_cluster), "r"(src_cta), "r"(bytes), "r"(rmbar) : "memory");
}
__device__ __forceinline__ void cluster_sync_all() {
    asm volatile("barrier.cluster.arrive.aligned;" ::: "memory");
    asm volatile("barrier.cluster.wait.aligned;" ::: "memory");
}

__device__ __forceinline__ float sigfast(float x) {
    return __fdividef(1.f, 1.f + __expf(-x));
}
__device__ __forceinline__ float tanhfast(float x) {
    return 1.f - 2.f * __fdividef(1.f, __expf(2.f * x) + 1.f);
}

// ------------------------------ gather ------------------------------------
__global__ void k_gather(const int* __restrict__ ids, const float* __restrict__ emb) {
    int idx = blockIdx.x * blockDim.x + threadIdx.x;   // SEQ * 125 float4
    if (idx < SEQ * 125) {
        int t = idx / 125, c = idx % 125;
        const float4* src = reinterpret_cast<const float4*>(emb + (size_t)ids[t] * EMB);
        reinterpret_cast<float4*>(g_x)[t * 125 + c] = src[c];
    }
}

// --------------------------- input projection GEMM ------------------------
__global__ void k_xproj(const float* __restrict__ wf, const float* __restrict__ wb,
                        const float* __restrict__ bihf, const float* __restrict__ bhhf,
                        const float* __restrict__ bihb, const float* __restrict__ bhhb) {
    const int dir = blockIdx.z;
    const float* __restrict__ W = dir ? wb : wf;
    __shared__ float As[16][68];
    __shared__ float Bs[16][68];
    const int m0 = blockIdx.y * 64, n0 = blockIdx.x * 64;
    const int tid = threadIdx.x;
    const int tx = tid & 15, ty = tid >> 4;
    float acc[4][4] = {};
    for (int k0 = 0; k0 < EMB; k0 += 16) {
        #pragma unroll
        for (int e = 0; e < 4; e++) {
            int L = tid + 256 * e;
            int r = L >> 4, kk = L & 15;
            bool kok = (k0 + kk) < EMB;
            int gm = m0 + r;
            int srcRow = dir ? (SEQ - 1 - gm) : gm;
            As[kk][r] = kok ? g_x[(size_t)srcRow * EMB + k0 + kk] : 0.f;
            int gn = n0 + r;
            Bs[kk][r] = (kok && gn < G4) ? W[(size_t)gn * EMB + k0 + kk] : 0.f;
        }
        __syncthreads();
        #pragma unroll
        for (int kk = 0; kk < 16; kk++) {
            float a[4], b[4];
            #pragma unroll
            for (int i = 0; i < 4; i++) a[i] = As[kk][ty * 4 + i];
            #pragma unroll
            for (int j = 0; j < 4; j++) b[j] = Bs[kk][tx * 4 + j];
            #pragma unroll
            for (int i = 0; i < 4; i++)
                #pragma unroll
                for (int j = 0; j < 4; j++) acc[i][j] += a[i] * b[j];
        }
        __syncthreads();
    }
    #pragma unroll
    for (int i = 0; i < 4; i++) {
        int gm = m0 + ty * 4 + i;
        #pragma unroll
        for (int j = 0; j < 4; j++) {
            int gn = n0 + tx * 4 + j;
            if (gn < G4) {
                float bias = dir ? (bihb[gn] + bhhb[gn]) : (bihf[gn] + bhhf[gn]);
                g_xproj[dir][(size_t)gm * G4 + gn] = acc[i][j] + bias;
            }
        }
    }
}

// ------------------------------ LSTM ---------------------------------------
// 2 clusters of 8 CTAs (one per direction). Each CTA owns 25 h elements
// (100 gate rows). W_hh kept in registers as packed f32x2 pairs over a
// zero-padded 224-float h layout (8 slices of 28). Per step: one thread
// waits the transaction mbarrier, dot via FFMA2 with pair-in-warp k-split,
// 25 threads run the cell, 8 threads bulk-copy the 112B slice to all peers.
__global__ void __launch_bounds__(256, 1) __cluster_dims__(NBLK, 1, 1)
k_lstm(const float* __restrict__ whf, const float* __restrict__ whb,
       const float* __restrict__ h0, const float* __restrict__ c0) {
    const int dir = blockIdx.x >> 3;
    uint32_t rank;
    asm("mov.u32 %0, %%cluster_ctarank;" : "=r"(rank));
    const int j0 = (int)rank * JS;
    const float* __restrict__ Whh = dir ? whb : whf;
    const int tid = threadIdx.x;
    const int wid = tid >> 5, lane = tid & 31;
    const int row = wid * 16 + (lane >> 1);   // 0..127, active < 100
    const int khalf = lane & 1;               // 0: pad-k [0..112), 1: [112..224)
    const bool act = row < ROWS;

    __shared__ __align__(16) float hbuf[2][HPAD];
    __shared__ float gsh[ROWS];
    __shared__ __align__(16) float hlocp[HP];
    __shared__ __align__(8) uint64_t mbar[2];

    // --- pack weights over padded layout: pos P -> (r=P/28, o=P%28), zero pad
    unsigned long long w2[56];
    int gr = 0;
    if (act) {
        int gate = row / JS, jj = row % JS;
        gr = gate * HID + j0 + jj;
        const float* wr = Whh + (size_t)gr * HID;
        #pragma unroll
        for (int p = 0; p < 56; p++) {
            int P0 = khalf * 112 + 2 * p;
            int r0 = P0 / HP, o0 = P0 % HP;
            int P1 = P0 + 1;
            int r1 = P1 / HP, o1 = P1 % HP;
            float lo = (o0 < JS) ? wr[r0 * JS + o0] : 0.f;
            float hi = (o1 < JS) ? wr[r1 * JS + o1] : 0.f;
            asm("mov.b64 %0, {%1, %2};" : "=l"(w2[p]) : "f"(lo), "f"(hi));
        }
    } else {
        #pragma unroll
        for (int p = 0; p < 56; p++) w2[p] = 0ull;
    }

    float cst = 0.f;
    if (tid < JS) cst = c0[dir * HID + j0 + tid];
    if (tid < HPAD) {
        int r = tid / HP, o = tid % HP;
        hbuf[0][tid] = (o < JS) ? h0[dir * HID + r * JS + o] : 0.f;
        hbuf[1][tid] = 0.f;
    }
    if (tid < HP) hlocp[tid] = 0.f;  // pads stay zero forever

    const uint32_t mb0 = smem_u32(&mbar[0]);
    const uint32_t mb1 = smem_u32(&mbar[1]);
    if (tid == 0) {
        mbar_init(mb0, 1);
        mbar_init(mb1, 1);
        mbar_arrive_expect_tx(mb0, TXB);   // receives h^2, h^4, ...
        mbar_arrive_expect_tx(mb1, TXB);   // receives h^1, h^3, ...
    }

    // 8 sender threads: thread t targets rank t; our slice lands at rank*HP.
    uint32_t dst0 = 0, dst1 = 0, rbm0 = 0, rbm1 = 0;
    const uint32_t src = smem_u32(hlocp);
    if (tid < NBLK) {
        dst0 = mapa32(smem_u32(&hbuf[0][rank * HP]), (uint32_t)tid);
        dst1 = mapa32(smem_u32(&hbuf[1][rank * HP]), (uint32_t)tid);
        rbm0 = mapa32(mb0, (uint32_t)tid);
        rbm1 = mapa32(mb1, (uint32_t)tid);
    }

    __syncthreads();
    cluster_sync_all();   // mbarriers + hbuf init visible cluster-wide

    const float* __restrict__ xp_base = &g_xproj[dir][0];

    for (int s = 0; s < SEQ; s++) {
        const int pin = s & 1;

        // prefetch xp before the barrier wait (independent of h)
        float xp = 0.f;
        if (act && khalf == 0) xp = __ldg(&xp_base[(size_t)s * G4 + gr]);

        if (s > 0) {
            if (tid == 0) {
                const uint32_t mb_in = pin ? mb1 : mb0;
                mbar_wait_cluster_acq(mb_in, (uint32_t)(((s - 1) >> 1) & 1));
                mbar_arrive_expect_tx(mb_in, TXB);   // re-arm for step s+2 traffic
            }
            __syncthreads();
        }

        // dot over padded 224: khalf half = 112 floats = 28 x 16B = 56 FFMA2
        if (wid < 7) {
            const ulonglong2* h2 =
                reinterpret_cast<const ulonglong2*>(&hbuf[pin][khalf * 112]);
            unsigned long long a0 = 0ull, a1 = 0ull;
            #pragma unroll
            for (int i = 0; i < 28; i++) {
                ulonglong2 hv = h2[i];
                asm("fma.rn.f32x2 %0, %1, %2, %0;"
                    : "+l"(a0) : "l"(w2[2 * i]), "l"(hv.x));
                asm("fma.rn.f32x2 %0, %1, %2, %0;"
                    : "+l"(a1) : "l"(w2[2 * i + 1]), "l"(hv.y));
            }
            float x0, x1, x2, x3;
            asm("mov.b64 {%0, %1}, %2;" : "=f"(x0), "=f"(x1) : "l"(a0));
            asm("mov.b64 {%0, %1}, %2;" : "=f"(x2), "=f"(x3) : "l"(a1));
            float acc = (x0 + x2) + (x1 + x3);
            acc += __shfl_xor_sync(0xffffffffu, acc, 1);   // combine k-halves
            if (act && khalf == 0) gsh[row] = acc + xp;
        }
        __syncthreads();

        if (tid < JS) {
            float gi = gsh[tid], gf = gsh[JS + tid];
            float gg = gsh[2 * JS + tid], go = gsh[3 * JS + tid];
            float c = sigfast(gf) * cst + sigfast(gi) * tanhfast(gg);
            float h = sigfast(go) * tanhfast(c);
            cst = c;
            hlocp[tid] = h;
            g_hseq[dir][(size_t)s * HID + j0 + tid] = h;
            asm volatile("fence.proxy.async.shared::cta;" ::: "memory");
        }
        __syncthreads();

        if (tid < NBLK && s < SEQ - 1) {
            const int pout = pin ^ 1;
            dsmem_bulk_copy(pout ? dst1 : dst0, src, SLICE_BYTES,
                            pout ? rbm1 : rbm0);
        }
    }
    // No CTA exits while peers may still reference its SMEM.
    cluster_sync_all();
}

// ------------------------------ linear -------------------------------------
__global__ void k_linear(const float* __restrict__ lw, const float* __restrict__ lb) {
    int t = blockIdx.x;
    __shared__ __align__(16) float hsm[2 * HID];
    int tid = threadIdx.x;                   // 64
    for (int i = tid; i < HID; i += 64) {
        hsm[i] = g_hseq[0][(size_t)t * HID + i];
        hsm[HID + i] = g_hseq[1][(size_t)(SEQ - 1 - t) * HID + i];
    }
    __syncthreads();
    if (tid < NT) {
        const float4* wr = reinterpret_cast<const float4*>(lw + (size_t)tid * 2 * HID);
        const float4* hv = reinterpret_cast<const float4*>(hsm);
        float acc = 0.f;
        #pragma unroll 5
        for (int i = 0; i < 100; i++) {
            float4 wv = wr[i]; float4 h4 = hv[i];
            acc += wv.x * h4.x + wv.y * h4.y + wv.z * h4.z + wv.w * h4.w;
        }
        g_feats[t * NT + tid] = acc + lb[tid];
    }
}

// ------------------------------ CRF ----------------------------------------
__global__ void __launch_bounds__(512, 1) k_crf(const float* __restrict__ trans,
                                                const int* __restrict__ tags,
                                                float* __restrict__ out, int out_size) {
    extern __shared__ unsigned char bpS[];   // SEQ*NT backpointers (block 1)
    __shared__ float trT[64][56];            // trT[j][i] = trans[i][j]
    __shared__ float alpha[2][64];
    __shared__ float wred[16];
    __shared__ float goldsh;
    const int tid = threadIdx.x;

    for (int L = tid; L < 64 * 56; L += 512) (&trT[0][0])[L] = 0.f;
    __syncthreads();
    for (int L = tid; L < NT * NT; L += 512) {
        int i = L / NT, j = L % NT;
        trT[j][i] = trans[L];
    }
    if (tid < 64) alpha[0][tid] = (tid == TSTART) ? 0.f : NEGV;
    __syncthreads();

    const int jg = tid >> 3, sub = tid & 7;

    if (blockIdx.x == 0) {
        float part = 0.f;
        for (int t = tid; t < SEQ; t += 512) {
            int prev = (t == 0) ? TSTART : tags[t - 1];
            int cur = tags[t];
            part += trans[prev * NT + cur] + g_feats[t * NT + cur];
        }
        #pragma unroll
        for (int d = 16; d > 0; d >>= 1) part += __shfl_xor_sync(0xffffffffu, part, d);
        if ((tid & 31) == 0) wred[tid >> 5] = part;
        __syncthreads();
        if (tid == 0) {
            float g = 0.f;
            for (int i2 = 0; i2 < 16; i2++) g += wred[i2];
            g += trans[tags[SEQ - 1] * NT + TEND];
            goldsh = g;
        }
        __syncthreads();

        int p = 0;
        for (int s = 0; s < SEQ; s++) {
            float fj = (jg < NT) ? g_feats[s * NT + jg] : 0.f;
            float vv[7];
            float m = -3.4e38f;
            #pragma unroll
            for (int q = 0; q < 7; q++) {
                int ii = sub + 8 * q;
                float v = (ii < NT) ? (alpha[p][ii] + trT[jg][ii]) + fj : -3.4e38f;
                vv[q] = v;
                m = fmaxf(m, v);
            }
            #pragma unroll
            for (int d = 1; d < 8; d <<= 1) m = fmaxf(m, __shfl_xor_sync(0xffffffffu, m, d));
            float sm = 0.f;
            #pragma unroll
            for (int q = 0; q < 7; q++) sm += __expf(vv[q] - m);
            #pragma unroll
            for (int d = 1; d < 8; d <<= 1) sm += __shfl_xor_sync(0xffffffffu, sm, d);
            if (sub == 0 && jg < NT) alpha[p ^ 1][jg] = m + __logf(sm);
            __syncthreads();
            p ^= 1;
        }
        if (tid == 0) {
            float m = -3.4e38f;
            for (int i2 = 0; i2 < NT; i2++)
                m = fmaxf(m, alpha[p][i2] + trans[i2 * NT + TEND]);
            float sm = 0.f;
            for (int i2 = 0; i2 < NT; i2++)
                sm += __expf((alpha[p][i2] + trans[i2 * NT + TEND]) - m);
            float logZ = m + __logf(sm);
            if (out_size > SEQ) out[SEQ] = logZ - goldsh;
        }
    } else {
        int p = 0;
        for (int s = 0; s < SEQ; s++) {
            float fj = (jg < NT) ? g_feats[s * NT + jg] : 0.f;
            float m = -3.4e38f;
            int mi = NT;
            #pragma unroll
            for (int q = 0; q < 7; q++) {
                int ii = sub + 8 * q;
                if (ii < NT) {
                    float v = (alpha[p][ii] + fj) + trT[jg][ii];
                    if (v > m) { m = v; mi = ii; }
                }
            }
            #pragma unroll
            for (int d = 1; d < 8; d <<= 1) {
                float om = __shfl_xor_sync(0xffffffffu, m, d);
                int omi = __shfl_xor_sync(0xffffffffu, mi, d);
                if (om > m || (om == m && omi < mi)) { m = om; mi = omi; }
            }
            if (sub == 0 && jg < NT) {
                alpha[p ^ 1][jg] = m;
                bpS[s * NT + jg] = (unsigned char)mi;
            }
            __syncthreads();
            p ^= 1;
        }
        if (tid == 0) {
            float bm = -3.4e38f;
            int best = 0;
            for (int i2 = 0; i2 < NT; i2++) {
                float v = alpha[p][i2] + trans[i2 * NT + TEND];
                if (v > bm) { bm = v; best = i2; }
            }
            int tag = best;
            out[SEQ - 1] = (float)tag;
            for (int t = SEQ - 2; t >= 0; t--) {
                tag = bpS[(t + 1) * NT + tag];
                out[t] = (float)tag;
            }
        }
    }
}

// ------------------------------ launch -------------------------------------
extern "C" void kernel_launch(void* const* d_in, const int* in_sizes, int n_in,
                              void* d_out, int out_size) {
    const int*   ids   = (const int*)d_in[0];
    const int*   tags  = (const int*)d_in[1];
    const float* emb   = (const float*)d_in[2];
    const float* wihf  = (const float*)d_in[3];
    const float* whhf  = (const float*)d_in[4];
    const float* bihf  = (const float*)d_in[5];
    const float* bhhf  = (const float*)d_in[6];
    const float* wihb  = (const float*)d_in[7];
    const float* whhb  = (const float*)d_in[8];
    const float* bihb  = (const float*)d_in[9];
    const float* bhhb  = (const float*)d_in[10];
    const float* lw    = (const float*)d_in[11];
    const float* lb    = (const float*)d_in[12];
    const float* trans = (const float*)d_in[13];
    const float* h0    = (const float*)d_in[14];
    const float* c0    = (const float*)d_in[15];
    float* out = (float*)d_out;

    (void)in_sizes; (void)n_in;

    cudaFuncSetAttribute(k_crf, cudaFuncAttributeMaxDynamicSharedMemorySize, SEQ * NT);

    k_gather<<<(SEQ * 125 + 255) / 256, 256>>>(ids, emb);
    k_xproj<<<dim3((G4 + 63) / 64, SEQ / 64, 2), 256>>>(wihf, wihb, bihf, bhhf, bihb, bhhb);
    k_lstm<<<2 * NBLK, 256>>>(whhf, whhb, h0, c0);
    k_linear<<<SEQ, 64>>>(lw, lb);
    k_crf<<<2, 512, SEQ * NT>>>(trans, tags, out, out_size);
}